// round 14
// baseline (speedup 1.0000x reference)
#include <cuda_runtime.h>
#include <cuda_bf16.h>
#include <math.h>
#include <cstdint>

// =====================================================================
// FrFTPool via mma.sync (sm_80 HMMA path), 3 launches total:
//  1) build_matrix_fused: chirp tables (thread-0 DP scalars, fp32
//     reduced sincos) + FrFT matrices M1..M4
//  2) combine_frag: A/B = crop-folded products -> mma A-fragment layout
//  3) frft_pool_main: per image D=Baug·Xaug^T, D2=A2aug·Taug^T, |.|
// bf16 hi/lo split folded into K (3 segments): rel err ~5e-6.
// =====================================================================

#define NBIG 128
#define NIMG 256
#define P16 136            // smem row pitch in bf16 units

__device__ __forceinline__ unsigned short bfh(float v) {
    return __bfloat16_as_ushort(__float2bfloat16_rn(v));
}
__device__ __forceinline__ float bff(unsigned short u) {
    return __bfloat162float(__ushort_as_bfloat16(u));
}
__device__ __forceinline__ void ldm_x2(uint32_t& r0, uint32_t& r1, uint32_t sa) {
    asm volatile("ldmatrix.sync.aligned.m8n8.x2.shared.b16 {%0,%1}, [%2];"
                 : "=r"(r0), "=r"(r1) : "r"(sa));
}
__device__ __forceinline__ void mma16816(float* c, uint4 a, uint32_t b0, uint32_t b1) {
    asm volatile("mma.sync.aligned.m16n8k16.row.col.f32.bf16.bf16.f32 "
                 "{%0,%1,%2,%3}, {%4,%5,%6,%7}, {%8,%9}, {%0,%1,%2,%3};"
                 : "+f"(c[0]), "+f"(c[1]), "+f"(c[2]), "+f"(c[3])
                 : "r"(a.x), "r"(a.y), "r"(a.z), "r"(a.w), "r"(b0), "r"(b1));
}
// double angle -> mod 2pi -> fp32 sincos (keeps double phase accuracy)
__device__ __forceinline__ float2 sincos_red(double th) {
    const double TWO_PI = 6.283185307179586476925286766559;
    double q = trunc(th * (1.0 / TWO_PI));
    float a = (float)(th - q * TWO_PI);
    float s, c;
    sincosf(a, &s, &c);
    return make_float2(c, s);
}

// ---------------- device scratch --------------------------------------
__device__ __align__(16) float2 d_M1[NBIG * NBIG];
__device__ __align__(16) float2 d_M2[NBIG * NBIG];
__device__ __align__(16) float2 d_M3[64 * 64];
__device__ __align__(16) float2 d_M4[64 * 64];
__device__ __align__(16) uint4  d_AF1[192 * 32];      // GEMM1 A-frags (8 mt x 24 kt)
__device__ __align__(16) uint4  d_AF2[384 * 32];      // GEMM2 A-frags (8 mt x 48 kt)

// ---------------- 1) tables + FrFT matrices, fused ---------------------
// matrix m: 0 -> order1 @N=128, 1 -> order2 @N=128,
//           2 -> -order1 @N=64,  3 -> -order2 @N=64
__global__ void build_matrix_fused(const float* __restrict__ order1,
                                   const float* __restrict__ order2) {
    int m = blockIdx.y;
    int N = (m < 2) ? NBIG : 64;
    int j = blockIdx.x;
    if (j >= N) return;

    __shared__ double sc_c, sc_kch;
    __shared__ float2 s_pref;
    __shared__ int    s_flip;
    __shared__ float2 Ks[4 * NBIG];
    __shared__ float2 Cs[2 * NBIG];
    __shared__ float  W[NBIG];
    __shared__ float2 KC[NBIG];

    int tid = threadIdx.x;
    if (tid == 0) {
        float ap = ((m == 0) || (m == 2)) ? order1[0] : order2[0];
        if (m >= 2) ap = -ap;
        double a = fmod((double)ap, 4.0);
        if (a < 0.0) a += 4.0;
        int flip = 0;
        if (a > 2.0) { flip = 1; a -= 2.0; }
        double alpha = a * M_PI * 0.5;
        double tana2 = tan(alpha * 0.5);
        double sina  = sin(alpha);
        double c     = M_PI / (4.0 * (double)N * sina);
        sc_c   = c;
        sc_kch = (M_PI / (double)N) * tana2 * 0.25;
        s_flip = flip;
        double ph = -(1.0 - a) * M_PI * 0.25;
        double sn, co; sincos(ph, &sn, &co);
        double sq = sqrt(c / M_PI);
        s_pref = make_float2((float)(co * sq), (float)(sn * sq));
    }
    __syncthreads();
    double c = sc_c, kch = sc_kch;

    for (int i = tid; i < 4 * N - 3; i += 128) {
        double mm = (double)(i - (2 * N - 2));
        Ks[i] = sincos_red(c * mm * mm);
    }
    for (int p = tid; p < 2 * N - 1; p += 128) {
        double n = (double)(p - (N - 1));
        Cs[p] = sincos_red(-kch * n * n);
    }
    if (tid < N)
        W[tid] = ((tid & 1) ? -2.0f : 2.0f) / ((float)M_PI * (float)(2 * tid + 1));
    __syncthreads();

    int off = 2 * N - 2;
    if (tid < N - 1) {
        float2 K = Ks[2 * j - 2 * tid - 1 + off];
        float2 C = Cs[2 * tid + 1];
        KC[tid] = make_float2(K.x * C.x - K.y * C.y, K.x * C.y + K.y * C.x);
    }
    __syncthreads();

    int k = tid;
    if (k >= N) return;
    int kk = s_flip ? (N - 1 - k) : k;

    float2 Ke = Ks[2 * (j - kk) + off];
    float2 Ce = Cs[2 * kk];
    float sr = Ke.x * Ce.x - Ke.y * Ce.y;
    float si = Ke.x * Ce.y + Ke.y * Ce.x;

    #pragma unroll 4
    for (int t = 0; t < N - 1; t++) {
        int u = t - kk;
        int idx = u ^ (u >> 31);
        float sv = W[idx];
        float2 kc = KC[t];
        sr = fmaf(kc.x, sv, sr);
        si = fmaf(kc.y, sv, si);
    }

    float2 pr = s_pref;
    float2 Cj = Cs[2 * j];
    float pcr = pr.x * Cj.x - pr.y * Cj.y;
    float pci = pr.x * Cj.y + pr.y * Cj.x;
    float2 outv;
    outv.x = pcr * sr - pci * si;
    outv.y = pcr * si + pci * sr;

    float2* M = (m == 0) ? d_M1 : (m == 1) ? d_M2 : (m == 2) ? d_M3 : d_M4;
    M[j * N + k] = outv;
}

// ---------------- 2) combine + fragpack fused --------------------------
// block (t<4, side): rows 16t..16t+15 of A (side 0) or B (side 1) into
// smem, then pack the mma A-fragments whose rows live in this tile.
__global__ void combine_frag() {
    int t = blockIdx.x;          // tile 0..3
    int side = blockIdx.y;       // 0 = A (GEMM2 frags), 1 = B (GEMM1 frags)
    __shared__ float2 Tile[16][128];

    int tid = threadIdx.x;       // 256
    const float2* L = side ? d_M3 : d_M4;
    const float2* R = side ? d_M1 : d_M2;

    // ---- compute 16 rows x 128 cols: thread = (row rt, col-octet) ----
    {
        int rt = tid >> 4;               // 0..15
        int i = 16 * t + rt;
        int h0 = (tid & 15) * 8;
        float ar[8], ai[8];
        #pragma unroll
        for (int e = 0; e < 8; e++) { ar[e] = 0.f; ai[e] = 0.f; }
        for (int p = 0; p < 64; p++) {
            float2 l2 = L[i * 64 + p];
            #pragma unroll
            for (int e = 0; e < 8; e++) {
                float2 r2 = R[(32 + p) * NBIG + h0 + e];
                ar[e] = fmaf(l2.x, r2.x, ar[e]);
                ar[e] = fmaf(-l2.y, r2.y, ar[e]);
                ai[e] = fmaf(l2.x, r2.y, ai[e]);
                ai[e] = fmaf(l2.y, r2.x, ai[e]);
            }
        }
        #pragma unroll
        for (int e = 0; e < 8; e++)
            Tile[rt][h0 + e] = make_float2(ar[e], ai[e]);
    }
    __syncthreads();

    // ---- pack fragments (index math identical to round-13 fragpack) ----
    if (side == 1) {
        // GEMM1 A-side = Baug: mt = t (re) and t+4 (im); 24 kt each.
        #pragma unroll
        for (int s = 0; s < 2; s++) {
            int mt = t + 4 * s;
            #pragma unroll
            for (int it = 0; it < 3; it++) {     // 24 kt * 32 lanes / 256
                int idx = tid + it * 256;
                int kt = idx >> 5, lane = idx & 31;
                int seg = kt >> 3, kb = (kt & 7) * 16;
                int gr = lane >> 2;
                int c0 = kb + 2 * (lane & 3);
                uint4 o;
                #pragma unroll
                for (int q = 0; q < 4; q++) {
                    int rloc = gr + ((q & 1) ? 8 : 0);      // row local
                    int cc = c0 + ((q >> 1) ? 8 : 0);
                    uint32_t r = 0;
                    #pragma unroll
                    for (int e = 0; e < 2; e++) {
                        float2 b = Tile[rloc][cc + e];
                        float v = (s == 0) ? b.x : b.y;
                        unsigned short hh = bfh(v);
                        unsigned short u = (seg == 2) ? bfh(v - bff(hh)) : hh;
                        r |= ((uint32_t)u) << (16 * e);
                    }
                    ((uint32_t*)&o)[q] = r;
                }
                d_AF1[(mt * 24 + kt) * 32 + lane] = o;
            }
        }
    } else {
        // GEMM2 A-side = A2aug: mt = t (rr<64) and t+4 (rr>=64); 48 kt each.
        #pragma unroll
        for (int s = 0; s < 2; s++) {
            #pragma unroll
            for (int it = 0; it < 6; it++) {     // 48 kt * 32 lanes / 256
                int idx = tid + it * 256;
                int kt = idx >> 5, lane = idx & 31;
                int seg = kt >> 4;
                int k256 = (kt & 15) * 16;
                int gr = lane >> 2;
                int c0 = k256 + 2 * (lane & 3);
                uint4 o;
                #pragma unroll
                for (int q = 0; q < 4; q++) {
                    int rloc = gr + ((q & 1) ? 8 : 0);
                    int cbase = c0 + ((q >> 1) ? 8 : 0);
                    uint32_t r = 0;
                    #pragma unroll
                    for (int e = 0; e < 2; e++) {
                        int cc = cbase + e;
                        int ri = cc >> 7, p = cc & 127;
                        float2 a = Tile[rloc][p];
                        float v = (s == 0) ? (ri ? -a.y : a.x)
                                           : (ri ?  a.x : a.y);
                        unsigned short hh = bfh(v);
                        unsigned short u = (seg == 1) ? bfh(v - bff(hh)) : hh;
                        r |= ((uint32_t)u) << (16 * e);
                    }
                    ((uint32_t*)&o)[q] = r;
                }
                d_AF2[((t + 4 * s) * 48 + kt) * 32 + lane] = o;
            }
        }
    }
}

// ---------------- 3) main tensor kernel (round-13 exact) ---------------
#define SMEM_BYTES (2 * 128 * P16 * 2)   // 69632

__global__ __launch_bounds__(256, 2)
void frft_pool_main(const float* __restrict__ x, float* __restrict__ out) {
    extern __shared__ char smem[];
    unsigned short* Xh = (unsigned short*)smem;   // plane0 [128][136]
    unsigned short* Xl = Xh + 128 * P16;          // plane1
    uint32_t sbase;
    {
        uint64_t g = (uint64_t)__cvta_generic_to_shared(smem);
        sbase = (uint32_t)g;
    }
    uint32_t plane0 = sbase;
    uint32_t plane1 = sbase + 128 * P16 * 2;

    int tid = threadIdx.x;
    int lane = tid & 31;
    int w = tid >> 5;          // warp 0..7
    int img = blockIdx.x;
    int gr = lane >> 2;
    int gc = 2 * (lane & 3);

    // ---- A) load X, split to bf16 h/l planes (row-major [p][k]) ----
    const float4* xg4 = (const float4*)(x + (size_t)img * (NBIG * NBIG));
    #pragma unroll
    for (int it = 0; it < 16; it++) {
        int idx = tid + it * 256;
        int p = idx >> 5;
        int q4 = (idx & 31) << 2;
        float4 v = xg4[idx];
        unsigned short h0 = bfh(v.x), h1 = bfh(v.y), h2 = bfh(v.z), h3 = bfh(v.w);
        uint2 hv, lv;
        hv.x = (uint32_t)h0 | ((uint32_t)h1 << 16);
        hv.y = (uint32_t)h2 | ((uint32_t)h3 << 16);
        lv.x = (uint32_t)bfh(v.x - bff(h0)) | ((uint32_t)bfh(v.y - bff(h1)) << 16);
        lv.y = (uint32_t)bfh(v.z - bff(h2)) | ((uint32_t)bfh(v.w - bff(h3)) << 16);
        *(uint2*)&Xh[p * P16 + q4] = hv;
        *(uint2*)&Xl[p * P16 + q4] = lv;
    }
    __syncthreads();

    // ---- B) GEMM1: D[n,p] = Baug·Xaug^T; warp w owns n rows 16w..16w+15
    float c[16][4];
    #pragma unroll
    for (int nt = 0; nt < 16; nt++)
        #pragma unroll
        for (int r = 0; r < 4; r++) c[nt][r] = 0.f;

    #pragma unroll 4
    for (int kt = 0; kt < 24; kt++) {
        uint4 af = d_AF1[(w * 24 + kt) * 32 + lane];
        uint32_t plane = ((kt >> 3) == 1) ? plane1 : plane0;  // X segs [h|l|h]
        int kb = (kt & 7) * 16;
        uint32_t ab = plane + (uint32_t)(((lane & 7) * P16 + kb + 8 * ((lane >> 3) & 1)) * 2);
        #pragma unroll
        for (int nt = 0; nt < 16; nt++) {
            uint32_t b0, b1;
            ldm_x2(b0, b1, ab + (uint32_t)(nt * 8 * P16 * 2));
            mma16816(c[nt], af, b0, b1);
        }
    }
    __syncthreads();

    // ---- C) split-store T planes (reuse smem): T[n][p] bf16 h/l ----
    unsigned short* Th = Xh;
    unsigned short* Tl = Xl;
    #pragma unroll
    for (int nt = 0; nt < 16; nt++) {
        int p = nt * 8 + gc;
        int n0 = 16 * w + gr;
        unsigned short hA0 = bfh(c[nt][0]), hA1 = bfh(c[nt][1]);
        unsigned short hB0 = bfh(c[nt][2]), hB1 = bfh(c[nt][3]);
        *(uint32_t*)&Th[n0 * P16 + p] =
            (uint32_t)hA0 | ((uint32_t)hA1 << 16);
        *(uint32_t*)&Tl[n0 * P16 + p] =
            (uint32_t)bfh(c[nt][0] - bff(hA0)) |
            ((uint32_t)bfh(c[nt][1] - bff(hA1)) << 16);
        *(uint32_t*)&Th[(n0 + 8) * P16 + p] =
            (uint32_t)hB0 | ((uint32_t)hB1 << 16);
        *(uint32_t*)&Tl[(n0 + 8) * P16 + p] =
            (uint32_t)bfh(c[nt][2] - bff(hB0)) |
            ((uint32_t)bfh(c[nt][3] - bff(hB1)) << 16);
    }
    __syncthreads();

    // ---- D) GEMM2: D2[r,j] = A2aug·Taug^T; warp w owns r rows 16w.. ----
    float d2[8][4];
    #pragma unroll
    for (int jt = 0; jt < 8; jt++)
        #pragma unroll
        for (int r = 0; r < 4; r++) d2[jt][r] = 0.f;

    #pragma unroll 4
    for (int kt = 0; kt < 48; kt++) {
        uint4 af = d_AF2[(w * 48 + kt) * 32 + lane];
        int seg = kt >> 4;
        uint32_t plane = (seg == 2) ? plane1 : plane0;   // T segs [h|h|l]
        int k256 = (kt & 15) * 16;
        int ri = k256 >> 7, kp = k256 & 127;
        uint32_t ab = plane + (uint32_t)((((64 * ri) + (lane & 7)) * P16 +
                                          kp + 8 * ((lane >> 3) & 1)) * 2);
        #pragma unroll
        for (int jt = 0; jt < 8; jt++) {
            uint32_t b0, b1;
            ldm_x2(b0, b1, ab + (uint32_t)(jt * 8 * P16 * 2));
            mma16816(d2[jt], af, b0, b1);
        }
    }
    __syncthreads();

    // ---- E) D2 -> smem f32 [128][68] ----
    float* D2s = (float*)smem;
    #pragma unroll
    for (int jt = 0; jt < 8; jt++) {
        int j = jt * 8 + gc;
        int r0 = 16 * w + gr;
        *(float2*)&D2s[r0 * 68 + j]       = make_float2(d2[jt][0], d2[jt][1]);
        *(float2*)&D2s[(r0 + 8) * 68 + j] = make_float2(d2[jt][2], d2[jt][3]);
    }
    __syncthreads();

    // ---- F) magnitudes ----
    float* og = out + (size_t)img * 4096;
    #pragma unroll
    for (int it = 0; it < 4; it++) {
        int idx = tid + it * 256;
        int i = idx >> 4;
        int jq = (idx & 15) << 2;
        float4 vr = *(float4*)&D2s[i * 68 + jq];
        float4 vi = *(float4*)&D2s[(i + 64) * 68 + jq];
        float4 o;
        o.x = sqrtf(vr.x * vr.x + vi.x * vi.x);
        o.y = sqrtf(vr.y * vr.y + vi.y * vi.y);
        o.z = sqrtf(vr.z * vr.z + vi.z * vi.z);
        o.w = sqrtf(vr.w * vr.w + vi.w * vi.w);
        *(float4*)&og[i * 64 + jq] = o;
    }
}

// ---------------------------------------------------------------------
extern "C" void kernel_launch(void* const* d_in, const int* in_sizes, int n_in,
                              void* d_out, int out_size) {
    const float* x  = (const float*)d_in[0];
    const float* o1 = (const float*)d_in[1];
    const float* o2 = (const float*)d_in[2];
    float* out = (float*)d_out;

    build_matrix_fused<<<dim3(NBIG, 4), 128>>>(o1, o2);
    combine_frag<<<dim3(4, 2), 256>>>();

    cudaFuncSetAttribute(frft_pool_main,
                         cudaFuncAttributeMaxDynamicSharedMemorySize, SMEM_BYTES);
    frft_pool_main<<<NIMG, 256, SMEM_BYTES>>>(x, out);
}

// round 15
// speedup vs baseline: 1.0379x; 1.0379x over previous
#include <cuda_runtime.h>
#include <cuda_bf16.h>
#include <math.h>
#include <cstdint>

// =====================================================================
// FrFTPool via mma.sync (sm_80 HMMA path), 4 launches:
//  1) build_tables: chirp tables (DP sincos, sliced over 32 blocks)
//  2) build_matrix: FrFT matrices M1..M4 (fp32, shared-KC trick)
//  3) combine_frag: crop-folded A/B -> mma A-fragment layout
//  4) frft_pool_main: per image D=Baug·Xaug^T, D2=A2aug·Taug^T, |.|
// bf16 hi/lo split folded into K (3 segments): rel err ~5e-6.
// =====================================================================

#define NBIG 128
#define NIMG 256
#define P16 136            // smem row pitch in bf16 units

__device__ __forceinline__ unsigned short bfh(float v) {
    return __bfloat16_as_ushort(__float2bfloat16_rn(v));
}
__device__ __forceinline__ float bff(unsigned short u) {
    return __bfloat162float(__ushort_as_bfloat16(u));
}
__device__ __forceinline__ void ldm_x4(uint32_t& r0, uint32_t& r1,
                                       uint32_t& r2, uint32_t& r3, uint32_t sa) {
    asm volatile("ldmatrix.sync.aligned.m8n8.x4.shared.b16 {%0,%1,%2,%3}, [%4];"
                 : "=r"(r0), "=r"(r1), "=r"(r2), "=r"(r3) : "r"(sa));
}
__device__ __forceinline__ void mma16816(float* c, uint4 a, uint32_t b0, uint32_t b1) {
    asm volatile("mma.sync.aligned.m16n8k16.row.col.f32.bf16.bf16.f32 "
                 "{%0,%1,%2,%3}, {%4,%5,%6,%7}, {%8,%9}, {%0,%1,%2,%3};"
                 : "+f"(c[0]), "+f"(c[1]), "+f"(c[2]), "+f"(c[3])
                 : "r"(a.x), "r"(a.y), "r"(a.z), "r"(a.w), "r"(b0), "r"(b1));
}

// ---------------- device scratch --------------------------------------
__device__ __align__(16) float2 d_M1[NBIG * NBIG];
__device__ __align__(16) float2 d_M2[NBIG * NBIG];
__device__ __align__(16) float2 d_M3[64 * 64];
__device__ __align__(16) float2 d_M4[64 * 64];
__device__ __align__(16) uint4  d_AF1[192 * 32];      // GEMM1 A-frags
__device__ __align__(16) uint4  d_AF2[384 * 32];      // GEMM2 A-frags

__device__ __align__(16) float2 d_Ktab[4][4 * NBIG];
__device__ __align__(16) float2 d_Ctab[4][2 * NBIG];
__device__ float2 d_pref[4];
__device__ int    d_flip[4];

// ---------------- 1) chirp tables (DP sincos, sliced over 32 blocks) --
__global__ void build_tables(const float* __restrict__ order1,
                             const float* __restrict__ order2) {
    int m = blockIdx.x;
    int s = blockIdx.y;
    int N = (m < 2) ? NBIG : 64;
    float ap = ((m == 0) || (m == 2)) ? order1[0] : order2[0];
    if (m >= 2) ap = -ap;

    double a = fmod((double)ap, 4.0);
    if (a < 0.0) a += 4.0;
    int flip = 0;
    if (a > 2.0) { flip = 1; a -= 2.0; }

    double alpha = a * M_PI * 0.5;
    double tana2 = tan(alpha * 0.5);
    double sina  = sin(alpha);
    double c     = M_PI / (4.0 * (double)N * sina);
    double kch   = (M_PI / (double)N) * tana2 * 0.25;

    int t = threadIdx.x;
    int i = s * 128 + t;
    if (i < 4 * N - 3) {
        double mm = (double)(i - (2 * N - 2));
        double sn, co; sincos(c * mm * mm, &sn, &co);
        d_Ktab[m][i] = make_float2((float)co, (float)sn);
    }
    if (t < 32) {
        int p = s * 32 + t;
        if (p < 2 * N - 1) {
            double n = (double)(p - (N - 1));
            double sn, co; sincos(-kch * n * n, &sn, &co);
            d_Ctab[m][p] = make_float2((float)co, (float)sn);
        }
    }
    if (s == 0 && t == 0) {
        double ph = -(1.0 - a) * M_PI * 0.25;
        double sn, co; sincos(ph, &sn, &co);
        double sc = sqrt(c / M_PI);
        d_pref[m] = make_float2((float)(co * sc), (float)(sn * sc));
        d_flip[m] = flip;
    }
}

// ---------------- 2) FrFT matrices from tables (fp32 only) ------------
__global__ void build_matrix() {
    int m = blockIdx.y;
    int N = (m < 2) ? NBIG : 64;
    int j = blockIdx.x;
    if (j >= N) return;

    __shared__ float2 Ks[4 * NBIG];
    __shared__ float2 Cs[2 * NBIG];
    __shared__ float  W[NBIG];
    __shared__ float2 KC[NBIG];

    int tid = threadIdx.x;
    for (int i = tid; i < 4 * N - 3; i += 128) Ks[i] = d_Ktab[m][i];
    for (int p = tid; p < 2 * N - 1; p += 128) Cs[p] = d_Ctab[m][p];
    if (tid < N)
        W[tid] = ((tid & 1) ? -2.0f : 2.0f) / ((float)M_PI * (float)(2 * tid + 1));
    __syncthreads();

    int off = 2 * N - 2;
    if (tid < N - 1) {
        float2 K = Ks[2 * j - 2 * tid - 1 + off];
        float2 C = Cs[2 * tid + 1];
        KC[tid] = make_float2(K.x * C.x - K.y * C.y, K.x * C.y + K.y * C.x);
    }
    __syncthreads();

    int k = tid;
    if (k >= N) return;
    int flip = d_flip[m];
    int kk = flip ? (N - 1 - k) : k;

    float2 Ke = Ks[2 * (j - kk) + off];
    float2 Ce = Cs[2 * kk];
    float sr = Ke.x * Ce.x - Ke.y * Ce.y;
    float si = Ke.x * Ce.y + Ke.y * Ce.x;

    #pragma unroll 4
    for (int t = 0; t < N - 1; t++) {
        int u = t - kk;
        int idx = u ^ (u >> 31);
        float sv = W[idx];
        float2 kc = KC[t];
        sr = fmaf(kc.x, sv, sr);
        si = fmaf(kc.y, sv, si);
    }

    float2 pr = d_pref[m];
    float2 Cj = Cs[2 * j];
    float pcr = pr.x * Cj.x - pr.y * Cj.y;
    float pci = pr.x * Cj.y + pr.y * Cj.x;
    float2 outv;
    outv.x = pcr * sr - pci * si;
    outv.y = pcr * si + pci * sr;

    float2* M = (m == 0) ? d_M1 : (m == 1) ? d_M2 : (m == 2) ? d_M3 : d_M4;
    M[j * N + k] = outv;
}

// ---------------- 3) combine + fragpack fused --------------------------
__global__ void combine_frag() {
    int t = blockIdx.x;          // tile 0..3
    int side = blockIdx.y;       // 0 = A (GEMM2 frags), 1 = B (GEMM1 frags)
    __shared__ float2 Tile[16][128];

    int tid = threadIdx.x;       // 256
    const float2* L = side ? d_M3 : d_M4;
    const float2* R = side ? d_M1 : d_M2;

    {
        int rt = tid >> 4;
        int i = 16 * t + rt;
        int h0 = (tid & 15) * 8;
        float ar[8], ai[8];
        #pragma unroll
        for (int e = 0; e < 8; e++) { ar[e] = 0.f; ai[e] = 0.f; }
        for (int p = 0; p < 64; p++) {
            float2 l2 = L[i * 64 + p];
            #pragma unroll
            for (int e = 0; e < 8; e++) {
                float2 r2 = R[(32 + p) * NBIG + h0 + e];
                ar[e] = fmaf(l2.x, r2.x, ar[e]);
                ar[e] = fmaf(-l2.y, r2.y, ar[e]);
                ai[e] = fmaf(l2.x, r2.y, ai[e]);
                ai[e] = fmaf(l2.y, r2.x, ai[e]);
            }
        }
        #pragma unroll
        for (int e = 0; e < 8; e++)
            Tile[rt][h0 + e] = make_float2(ar[e], ai[e]);
    }
    __syncthreads();

    if (side == 1) {
        #pragma unroll
        for (int s = 0; s < 2; s++) {
            int mt = t + 4 * s;
            #pragma unroll
            for (int it = 0; it < 3; it++) {
                int idx = tid + it * 256;
                int kt = idx >> 5, lane = idx & 31;
                int seg = kt >> 3, kb = (kt & 7) * 16;
                int gr = lane >> 2;
                int c0 = kb + 2 * (lane & 3);
                uint4 o;
                #pragma unroll
                for (int q = 0; q < 4; q++) {
                    int rloc = gr + ((q & 1) ? 8 : 0);
                    int cc = c0 + ((q >> 1) ? 8 : 0);
                    uint32_t r = 0;
                    #pragma unroll
                    for (int e = 0; e < 2; e++) {
                        float2 b = Tile[rloc][cc + e];
                        float v = (s == 0) ? b.x : b.y;
                        unsigned short hh = bfh(v);
                        unsigned short u = (seg == 2) ? bfh(v - bff(hh)) : hh;
                        r |= ((uint32_t)u) << (16 * e);
                    }
                    ((uint32_t*)&o)[q] = r;
                }
                d_AF1[(mt * 24 + kt) * 32 + lane] = o;
            }
        }
    } else {
        #pragma unroll
        for (int s = 0; s < 2; s++) {
            #pragma unroll
            for (int it = 0; it < 6; it++) {
                int idx = tid + it * 256;
                int kt = idx >> 5, lane = idx & 31;
                int seg = kt >> 4;
                int k256 = (kt & 15) * 16;
                int gr = lane >> 2;
                int c0 = k256 + 2 * (lane & 3);
                uint4 o;
                #pragma unroll
                for (int q = 0; q < 4; q++) {
                    int rloc = gr + ((q & 1) ? 8 : 0);
                    int cbase = c0 + ((q >> 1) ? 8 : 0);
                    uint32_t r = 0;
                    #pragma unroll
                    for (int e = 0; e < 2; e++) {
                        int cc = cbase + e;
                        int ri = cc >> 7, p = cc & 127;
                        float2 a = Tile[rloc][p];
                        float v = (s == 0) ? (ri ? -a.y : a.x)
                                           : (ri ?  a.x : a.y);
                        unsigned short hh = bfh(v);
                        unsigned short u = (seg == 1) ? bfh(v - bff(hh)) : hh;
                        r |= ((uint32_t)u) << (16 * e);
                    }
                    ((uint32_t*)&o)[q] = r;
                }
                d_AF2[((t + 4 * s) * 48 + kt) * 32 + lane] = o;
            }
        }
    }
}

// ---------------- 4) main tensor kernel (ldmatrix.x4) ------------------
#define SMEM_BYTES (2 * 128 * P16 * 2)   // 69632

__global__ __launch_bounds__(256, 2)
void frft_pool_main(const float* __restrict__ x, float* __restrict__ out) {
    extern __shared__ char smem[];
    unsigned short* Xh = (unsigned short*)smem;   // plane0 [128][136]
    unsigned short* Xl = Xh + 128 * P16;          // plane1
    uint32_t sbase;
    {
        uint64_t g = (uint64_t)__cvta_generic_to_shared(smem);
        sbase = (uint32_t)g;
    }
    uint32_t plane0 = sbase;
    uint32_t plane1 = sbase + 128 * P16 * 2;

    int tid = threadIdx.x;
    int lane = tid & 31;
    int w = tid >> 5;
    int img = blockIdx.x;
    int gr = lane >> 2;
    int gc = 2 * (lane & 3);
    // ldmatrix.x4 row/col offset: rows (lane&7)+8*(lane>>4), col-half (lane>>3)&1
    uint32_t x4off = (uint32_t)((((lane & 7) + 8 * (lane >> 4)) * P16 +
                                 8 * ((lane >> 3) & 1)) * 2);

    // ---- A) load X, split to bf16 h/l planes (row-major [p][k]) ----
    const float4* xg4 = (const float4*)(x + (size_t)img * (NBIG * NBIG));
    #pragma unroll
    for (int it = 0; it < 16; it++) {
        int idx = tid + it * 256;
        int p = idx >> 5;
        int q4 = (idx & 31) << 2;
        float4 v = xg4[idx];
        unsigned short h0 = bfh(v.x), h1 = bfh(v.y), h2 = bfh(v.z), h3 = bfh(v.w);
        uint2 hv, lv;
        hv.x = (uint32_t)h0 | ((uint32_t)h1 << 16);
        hv.y = (uint32_t)h2 | ((uint32_t)h3 << 16);
        lv.x = (uint32_t)bfh(v.x - bff(h0)) | ((uint32_t)bfh(v.y - bff(h1)) << 16);
        lv.y = (uint32_t)bfh(v.z - bff(h2)) | ((uint32_t)bfh(v.w - bff(h3)) << 16);
        *(uint2*)&Xh[p * P16 + q4] = hv;
        *(uint2*)&Xl[p * P16 + q4] = lv;
    }
    __syncthreads();

    // ---- B) GEMM1: D[n,p] = Baug·Xaug^T; warp w owns n rows 16w..16w+15
    float c[16][4];
    #pragma unroll
    for (int nt = 0; nt < 16; nt++)
        #pragma unroll
        for (int r = 0; r < 4; r++) c[nt][r] = 0.f;

    #pragma unroll 4
    for (int kt = 0; kt < 24; kt++) {
        uint4 af = d_AF1[(w * 24 + kt) * 32 + lane];
        uint32_t plane = ((kt >> 3) == 1) ? plane1 : plane0;  // X segs [h|l|h]
        int kb = (kt & 7) * 16;
        uint32_t ab = plane + x4off + (uint32_t)(kb * 2);
        #pragma unroll
        for (int nt = 0; nt < 16; nt += 2) {
            uint32_t b0, b1, b2, b3;
            ldm_x4(b0, b1, b2, b3, ab + (uint32_t)(nt * 8 * P16 * 2));
            mma16816(c[nt],     af, b0, b1);
            mma16816(c[nt + 1], af, b2, b3);
        }
    }
    __syncthreads();

    // ---- C) split-store T planes (reuse smem): T[n][p] bf16 h/l ----
    unsigned short* Th = Xh;
    unsigned short* Tl = Xl;
    #pragma unroll
    for (int nt = 0; nt < 16; nt++) {
        int p = nt * 8 + gc;
        int n0 = 16 * w + gr;
        unsigned short hA0 = bfh(c[nt][0]), hA1 = bfh(c[nt][1]);
        unsigned short hB0 = bfh(c[nt][2]), hB1 = bfh(c[nt][3]);
        *(uint32_t*)&Th[n0 * P16 + p] =
            (uint32_t)hA0 | ((uint32_t)hA1 << 16);
        *(uint32_t*)&Tl[n0 * P16 + p] =
            (uint32_t)bfh(c[nt][0] - bff(hA0)) |
            ((uint32_t)bfh(c[nt][1] - bff(hA1)) << 16);
        *(uint32_t*)&Th[(n0 + 8) * P16 + p] =
            (uint32_t)hB0 | ((uint32_t)hB1 << 16);
        *(uint32_t*)&Tl[(n0 + 8) * P16 + p] =
            (uint32_t)bfh(c[nt][2] - bff(hB0)) |
            ((uint32_t)bfh(c[nt][3] - bff(hB1)) << 16);
    }
    __syncthreads();

    // ---- D) GEMM2: D2[r,j] = A2aug·Taug^T; warp w owns r rows 16w.. ----
    float d2[8][4];
    #pragma unroll
    for (int jt = 0; jt < 8; jt++)
        #pragma unroll
        for (int r = 0; r < 4; r++) d2[jt][r] = 0.f;

    #pragma unroll 4
    for (int kt = 0; kt < 48; kt++) {
        uint4 af = d_AF2[(w * 48 + kt) * 32 + lane];
        int seg = kt >> 4;
        uint32_t plane = (seg == 2) ? plane1 : plane0;   // T segs [h|h|l]
        int k256 = (kt & 15) * 16;
        int ri = k256 >> 7, kp = k256 & 127;
        uint32_t ab = plane + x4off + (uint32_t)((64 * ri * P16 + kp) * 2);
        #pragma unroll
        for (int jt = 0; jt < 8; jt += 2) {
            uint32_t b0, b1, b2, b3;
            ldm_x4(b0, b1, b2, b3, ab + (uint32_t)(jt * 8 * P16 * 2));
            mma16816(d2[jt],     af, b0, b1);
            mma16816(d2[jt + 1], af, b2, b3);
        }
    }
    __syncthreads();

    // ---- E) D2 -> smem f32 [128][68] ----
    float* D2s = (float*)smem;
    #pragma unroll
    for (int jt = 0; jt < 8; jt++) {
        int j = jt * 8 + gc;
        int r0 = 16 * w + gr;
        *(float2*)&D2s[r0 * 68 + j]       = make_float2(d2[jt][0], d2[jt][1]);
        *(float2*)&D2s[(r0 + 8) * 68 + j] = make_float2(d2[jt][2], d2[jt][3]);
    }
    __syncthreads();

    // ---- F) magnitudes ----
    float* og = out + (size_t)img * 4096;
    #pragma unroll
    for (int it = 0; it < 4; it++) {
        int idx = tid + it * 256;
        int i = idx >> 4;
        int jq = (idx & 15) << 2;
        float4 vr = *(float4*)&D2s[i * 68 + jq];
        float4 vi = *(float4*)&D2s[(i + 64) * 68 + jq];
        float4 o;
        o.x = sqrtf(vr.x * vr.x + vi.x * vi.x);
        o.y = sqrtf(vr.y * vr.y + vi.y * vi.y);
        o.z = sqrtf(vr.z * vr.z + vi.z * vi.z);
        o.w = sqrtf(vr.w * vr.w + vi.w * vi.w);
        *(float4*)&og[i * 64 + jq] = o;
    }
}

// ---------------------------------------------------------------------
extern "C" void kernel_launch(void* const* d_in, const int* in_sizes, int n_in,
                              void* d_out, int out_size) {
    const float* x  = (const float*)d_in[0];
    const float* o1 = (const float*)d_in[1];
    const float* o2 = (const float*)d_in[2];
    float* out = (float*)d_out;

    build_tables<<<dim3(4, 8), 128>>>(o1, o2);
    build_matrix<<<dim3(NBIG, 4), 128>>>();
    combine_frag<<<dim3(4, 2), 256>>>();

    cudaFuncSetAttribute(frft_pool_main,
                         cudaFuncAttributeMaxDynamicSharedMemorySize, SMEM_BYTES);
    frft_pool_main<<<NIMG, 256, SMEM_BYTES>>>(x, out);
}

// round 16
// speedup vs baseline: 1.2988x; 1.2513x over previous
#include <cuda_runtime.h>
#include <cuda_bf16.h>
#include <math.h>
#include <cstdint>

// =====================================================================
// FrFTPool via mma.sync (sm_80 HMMA path), 5 launches (wide prep):
//  1) build_tables: chirp tables (DP sincos, sliced over 32 blocks)
//  2) build_matrix: FrFT matrices M1..M4 (fp32, shared-KC trick)
//  3) combine: A = M4·M2[32:96], B = M3·M1[32:96]   (128 blocks)
//  4) fragpack: A/B -> mma A-fragment layout         (72 blocks)
//  5) frft_pool_main: per image D=Baug·Xaug^T, D2=A2aug·Taug^T, |.|
// bf16 hi/lo split folded into K (3 segments): rel err ~5e-6.
// =====================================================================

#define NBIG 128
#define NIMG 256
#define P16 136            // smem row pitch in bf16 units

__device__ __forceinline__ unsigned short bfh(float v) {
    return __bfloat16_as_ushort(__float2bfloat16_rn(v));
}
__device__ __forceinline__ float bff(unsigned short u) {
    return __bfloat162float(__ushort_as_bfloat16(u));
}
__device__ __forceinline__ void ldm_x4(uint32_t& r0, uint32_t& r1,
                                       uint32_t& r2, uint32_t& r3, uint32_t sa) {
    asm volatile("ldmatrix.sync.aligned.m8n8.x4.shared.b16 {%0,%1,%2,%3}, [%4];"
                 : "=r"(r0), "=r"(r1), "=r"(r2), "=r"(r3) : "r"(sa));
}
__device__ __forceinline__ void mma16816(float* c, uint4 a, uint32_t b0, uint32_t b1) {
    asm volatile("mma.sync.aligned.m16n8k16.row.col.f32.bf16.bf16.f32 "
                 "{%0,%1,%2,%3}, {%4,%5,%6,%7}, {%8,%9}, {%0,%1,%2,%3};"
                 : "+f"(c[0]), "+f"(c[1]), "+f"(c[2]), "+f"(c[3])
                 : "r"(a.x), "r"(a.y), "r"(a.z), "r"(a.w), "r"(b0), "r"(b1));
}

// ---------------- device scratch --------------------------------------
__device__ __align__(16) float2 d_M1[NBIG * NBIG];
__device__ __align__(16) float2 d_M2[NBIG * NBIG];
__device__ __align__(16) float2 d_M3[64 * 64];
__device__ __align__(16) float2 d_M4[64 * 64];
__device__ __align__(16) float2 d_Ac[64 * 128];       // A = M4·M2[32:96]
__device__ __align__(16) float2 d_Bc[64 * 128];       // B = M3·M1[32:96]
__device__ __align__(16) uint4  d_AF1[192 * 32];      // GEMM1 A-frags
__device__ __align__(16) uint4  d_AF2[384 * 32];      // GEMM2 A-frags

__device__ __align__(16) float2 d_Ktab[4][4 * NBIG];
__device__ __align__(16) float2 d_Ctab[4][2 * NBIG];
__device__ float2 d_pref[4];
__device__ int    d_flip[4];

// ---------------- 1) chirp tables (DP sincos, sliced over 32 blocks) --
__global__ void build_tables(const float* __restrict__ order1,
                             const float* __restrict__ order2) {
    int m = blockIdx.x;
    int s = blockIdx.y;
    int N = (m < 2) ? NBIG : 64;
    float ap = ((m == 0) || (m == 2)) ? order1[0] : order2[0];
    if (m >= 2) ap = -ap;

    double a = fmod((double)ap, 4.0);
    if (a < 0.0) a += 4.0;
    int flip = 0;
    if (a > 2.0) { flip = 1; a -= 2.0; }

    double alpha = a * M_PI * 0.5;
    double tana2 = tan(alpha * 0.5);
    double sina  = sin(alpha);
    double c     = M_PI / (4.0 * (double)N * sina);
    double kch   = (M_PI / (double)N) * tana2 * 0.25;

    int t = threadIdx.x;
    int i = s * 128 + t;
    if (i < 4 * N - 3) {
        double mm = (double)(i - (2 * N - 2));
        double sn, co; sincos(c * mm * mm, &sn, &co);
        d_Ktab[m][i] = make_float2((float)co, (float)sn);
    }
    if (t < 32) {
        int p = s * 32 + t;
        if (p < 2 * N - 1) {
            double n = (double)(p - (N - 1));
            double sn, co; sincos(-kch * n * n, &sn, &co);
            d_Ctab[m][p] = make_float2((float)co, (float)sn);
        }
    }
    if (s == 0 && t == 0) {
        double ph = -(1.0 - a) * M_PI * 0.25;
        double sn, co; sincos(ph, &sn, &co);
        double sc = sqrt(c / M_PI);
        d_pref[m] = make_float2((float)(co * sc), (float)(sn * sc));
        d_flip[m] = flip;
    }
}

// ---------------- 2) FrFT matrices from tables (fp32 only) ------------
__global__ void build_matrix() {
    int m = blockIdx.y;
    int N = (m < 2) ? NBIG : 64;
    int j = blockIdx.x;
    if (j >= N) return;

    __shared__ float2 Ks[4 * NBIG];
    __shared__ float2 Cs[2 * NBIG];
    __shared__ float  W[NBIG];
    __shared__ float2 KC[NBIG];

    int tid = threadIdx.x;
    for (int i = tid; i < 4 * N - 3; i += 128) Ks[i] = d_Ktab[m][i];
    for (int p = tid; p < 2 * N - 1; p += 128) Cs[p] = d_Ctab[m][p];
    if (tid < N)
        W[tid] = ((tid & 1) ? -2.0f : 2.0f) / ((float)M_PI * (float)(2 * tid + 1));
    __syncthreads();

    int off = 2 * N - 2;
    if (tid < N - 1) {
        float2 K = Ks[2 * j - 2 * tid - 1 + off];
        float2 C = Cs[2 * tid + 1];
        KC[tid] = make_float2(K.x * C.x - K.y * C.y, K.x * C.y + K.y * C.x);
    }
    __syncthreads();

    int k = tid;
    if (k >= N) return;
    int flip = d_flip[m];
    int kk = flip ? (N - 1 - k) : k;

    float2 Ke = Ks[2 * (j - kk) + off];
    float2 Ce = Cs[2 * kk];
    float sr = Ke.x * Ce.x - Ke.y * Ce.y;
    float si = Ke.x * Ce.y + Ke.y * Ce.x;

    #pragma unroll 4
    for (int t = 0; t < N - 1; t++) {
        int u = t - kk;
        int idx = u ^ (u >> 31);
        float sv = W[idx];
        float2 kc = KC[t];
        sr = fmaf(kc.x, sv, sr);
        si = fmaf(kc.y, sv, si);
    }

    float2 pr = d_pref[m];
    float2 Cj = Cs[2 * j];
    float pcr = pr.x * Cj.x - pr.y * Cj.y;
    float pci = pr.x * Cj.y + pr.y * Cj.x;
    float2 outv;
    outv.x = pcr * sr - pci * si;
    outv.y = pcr * si + pci * sr;

    float2* M = (m == 0) ? d_M1 : (m == 1) ? d_M2 : (m == 2) ? d_M3 : d_M4;
    M[j * N + k] = outv;
}

// ---------------- 3) combine: A = M4·M2[32:96], B = M3·M1[32:96] ------
__global__ void combine() {
    int i = blockIdx.x;          // 0..63
    int h = threadIdx.x;         // 0..127
    const float2* L = blockIdx.y ? d_M3 : d_M4;   // 64x64
    const float2* R = blockIdx.y ? d_M1 : d_M2;   // 128x128
    float ar = 0.f, ai = 0.f;
    #pragma unroll 4
    for (int p = 0; p < 64; p++) {
        float2 l2 = L[i * 64 + p];
        float2 r2 = R[(32 + p) * NBIG + h];
        ar += l2.x * r2.x - l2.y * r2.y;
        ai += l2.x * r2.y + l2.y * r2.x;
    }
    float2* T = blockIdx.y ? d_Bc : d_Ac;
    T[i * 128 + h] = make_float2(ar, ai);
}

// ---------------- 4) fragpack: constant operands -> A-frag layout ------
__device__ __forceinline__ uint32_t packB1(int n, int kk, int seg) {
    uint32_t r = 0;
    #pragma unroll
    for (int e = 0; e < 2; e++) {
        float2 b = d_Bc[(n & 63) * 128 + kk + e];
        float v = (n < 64) ? b.x : b.y;
        unsigned short hh = bfh(v);
        unsigned short u = (seg == 2) ? bfh(v - bff(hh)) : hh;
        r |= ((uint32_t)u) << (16 * e);
    }
    return r;
}
__device__ __forceinline__ uint32_t packA2(int rr, int c, int seg) {
    uint32_t r = 0;
    #pragma unroll
    for (int e = 0; e < 2; e++) {
        int cc = c + e;
        int ri = cc >> 7, p = cc & 127;
        float2 a = d_Ac[(rr & 63) * 128 + p];
        float v = (rr < 64) ? (ri ? -a.y : a.x) : (ri ? a.x : a.y);
        unsigned short hh = bfh(v);
        unsigned short u = (seg == 1) ? bfh(v - bff(hh)) : hh;
        r |= ((uint32_t)u) << (16 * e);
    }
    return r;
}
__global__ void fragpack() {
    int idx = blockIdx.x * 256 + threadIdx.x;     // < 18432
    int lane = idx & 31, t = idx >> 5;
    if (t < 192) {
        int mt = t / 24, kt = t % 24;
        int seg = kt >> 3, kb = (kt & 7) * 16;
        int r0 = 16 * mt + (lane >> 2);
        int c0 = kb + 2 * (lane & 3);
        uint4 o;
        o.x = packB1(r0,     c0,     seg);
        o.y = packB1(r0 + 8, c0,     seg);
        o.z = packB1(r0,     c0 + 8, seg);
        o.w = packB1(r0 + 8, c0 + 8, seg);
        d_AF1[t * 32 + lane] = o;
    } else {
        int t2 = t - 192;
        int mt = t2 / 48, kt = t2 % 48;
        int seg = kt >> 4;
        int k256 = (kt & 15) * 16;
        int r0 = 16 * mt + (lane >> 2);
        int c0 = k256 + 2 * (lane & 3);
        uint4 o;
        o.x = packA2(r0,     c0,     seg);
        o.y = packA2(r0 + 8, c0,     seg);
        o.z = packA2(r0,     c0 + 8, seg);
        o.w = packA2(r0 + 8, c0 + 8, seg);
        d_AF2[t2 * 32 + lane] = o;
    }
}

// ---------------- 5) main tensor kernel (ldmatrix.x4) ------------------
#define SMEM_BYTES (2 * 128 * P16 * 2)   // 69632

__global__ __launch_bounds__(256, 2)
void frft_pool_main(const float* __restrict__ x, float* __restrict__ out) {
    extern __shared__ char smem[];
    unsigned short* Xh = (unsigned short*)smem;   // plane0 [128][136]
    unsigned short* Xl = Xh + 128 * P16;          // plane1
    uint32_t sbase;
    {
        uint64_t g = (uint64_t)__cvta_generic_to_shared(smem);
        sbase = (uint32_t)g;
    }
    uint32_t plane0 = sbase;
    uint32_t plane1 = sbase + 128 * P16 * 2;

    int tid = threadIdx.x;
    int lane = tid & 31;
    int w = tid >> 5;
    int img = blockIdx.x;
    int gr = lane >> 2;
    int gc = 2 * (lane & 3);
    // ldmatrix.x4: rows (lane&7)+8*(lane>>4), col-half 8*((lane>>3)&1)
    uint32_t x4off = (uint32_t)((((lane & 7) + 8 * (lane >> 4)) * P16 +
                                 8 * ((lane >> 3) & 1)) * 2);

    // ---- A) load X, split to bf16 h/l planes (row-major [p][k]) ----
    const float4* xg4 = (const float4*)(x + (size_t)img * (NBIG * NBIG));
    #pragma unroll
    for (int it = 0; it < 16; it++) {
        int idx = tid + it * 256;
        int p = idx >> 5;
        int q4 = (idx & 31) << 2;
        float4 v = xg4[idx];
        unsigned short h0 = bfh(v.x), h1 = bfh(v.y), h2 = bfh(v.z), h3 = bfh(v.w);
        uint2 hv, lv;
        hv.x = (uint32_t)h0 | ((uint32_t)h1 << 16);
        hv.y = (uint32_t)h2 | ((uint32_t)h3 << 16);
        lv.x = (uint32_t)bfh(v.x - bff(h0)) | ((uint32_t)bfh(v.y - bff(h1)) << 16);
        lv.y = (uint32_t)bfh(v.z - bff(h2)) | ((uint32_t)bfh(v.w - bff(h3)) << 16);
        *(uint2*)&Xh[p * P16 + q4] = hv;
        *(uint2*)&Xl[p * P16 + q4] = lv;
    }
    __syncthreads();

    // ---- B) GEMM1: D[n,p] = Baug·Xaug^T; warp w owns n rows 16w..16w+15
    float c[16][4];
    #pragma unroll
    for (int nt = 0; nt < 16; nt++)
        #pragma unroll
        for (int r = 0; r < 4; r++) c[nt][r] = 0.f;

    #pragma unroll 4
    for (int kt = 0; kt < 24; kt++) {
        uint4 af = d_AF1[(w * 24 + kt) * 32 + lane];
        uint32_t plane = ((kt >> 3) == 1) ? plane1 : plane0;  // X segs [h|l|h]
        int kb = (kt & 7) * 16;
        uint32_t ab = plane + x4off + (uint32_t)(kb * 2);
        #pragma unroll
        for (int nt = 0; nt < 16; nt += 2) {
            uint32_t b0, b1, b2, b3;
            ldm_x4(b0, b1, b2, b3, ab + (uint32_t)(nt * 8 * P16 * 2));
            mma16816(c[nt],     af, b0, b1);
            mma16816(c[nt + 1], af, b2, b3);
        }
    }
    __syncthreads();

    // ---- C) split-store T planes (reuse smem): T[n][p] bf16 h/l ----
    unsigned short* Th = Xh;
    unsigned short* Tl = Xl;
    #pragma unroll
    for (int nt = 0; nt < 16; nt++) {
        int p = nt * 8 + gc;
        int n0 = 16 * w + gr;
        unsigned short hA0 = bfh(c[nt][0]), hA1 = bfh(c[nt][1]);
        unsigned short hB0 = bfh(c[nt][2]), hB1 = bfh(c[nt][3]);
        *(uint32_t*)&Th[n0 * P16 + p] =
            (uint32_t)hA0 | ((uint32_t)hA1 << 16);
        *(uint32_t*)&Tl[n0 * P16 + p] =
            (uint32_t)bfh(c[nt][0] - bff(hA0)) |
            ((uint32_t)bfh(c[nt][1] - bff(hA1)) << 16);
        *(uint32_t*)&Th[(n0 + 8) * P16 + p] =
            (uint32_t)hB0 | ((uint32_t)hB1 << 16);
        *(uint32_t*)&Tl[(n0 + 8) * P16 + p] =
            (uint32_t)bfh(c[nt][2] - bff(hB0)) |
            ((uint32_t)bfh(c[nt][3] - bff(hB1)) << 16);
    }
    __syncthreads();

    // ---- D) GEMM2: D2[r,j] = A2aug·Taug^T; warp w owns r rows 16w.. ----
    float d2[8][4];
    #pragma unroll
    for (int jt = 0; jt < 8; jt++)
        #pragma unroll
        for (int r = 0; r < 4; r++) d2[jt][r] = 0.f;

    #pragma unroll 4
    for (int kt = 0; kt < 48; kt++) {
        uint4 af = d_AF2[(w * 48 + kt) * 32 + lane];
        int seg = kt >> 4;
        uint32_t plane = (seg == 2) ? plane1 : plane0;   // T segs [h|h|l]
        int k256 = (kt & 15) * 16;
        int ri = k256 >> 7, kp = k256 & 127;
        uint32_t ab = plane + x4off + (uint32_t)((64 * ri * P16 + kp) * 2);
        #pragma unroll
        for (int jt = 0; jt < 8; jt += 2) {
            uint32_t b0, b1, b2, b3;
            ldm_x4(b0, b1, b2, b3, ab + (uint32_t)(jt * 8 * P16 * 2));
            mma16816(d2[jt],     af, b0, b1);
            mma16816(d2[jt + 1], af, b2, b3);
        }
    }
    __syncthreads();

    // ---- E) D2 -> smem f32 [128][68] ----
    float* D2s = (float*)smem;
    #pragma unroll
    for (int jt = 0; jt < 8; jt++) {
        int j = jt * 8 + gc;
        int r0 = 16 * w + gr;
        *(float2*)&D2s[r0 * 68 + j]       = make_float2(d2[jt][0], d2[jt][1]);
        *(float2*)&D2s[(r0 + 8) * 68 + j] = make_float2(d2[jt][2], d2[jt][3]);
    }
    __syncthreads();

    // ---- F) magnitudes ----
    float* og = out + (size_t)img * 4096;
    #pragma unroll
    for (int it = 0; it < 4; it++) {
        int idx = tid + it * 256;
        int i = idx >> 4;
        int jq = (idx & 15) << 2;
        float4 vr = *(float4*)&D2s[i * 68 + jq];
        float4 vi = *(float4*)&D2s[(i + 64) * 68 + jq];
        float4 o;
        o.x = sqrtf(vr.x * vr.x + vi.x * vi.x);
        o.y = sqrtf(vr.y * vr.y + vi.y * vi.y);
        o.z = sqrtf(vr.z * vr.z + vi.z * vi.z);
        o.w = sqrtf(vr.w * vr.w + vi.w * vi.w);
        *(float4*)&og[i * 64 + jq] = o;
    }
}

// ---------------------------------------------------------------------
extern "C" void kernel_launch(void* const* d_in, const int* in_sizes, int n_in,
                              void* d_out, int out_size) {
    const float* x  = (const float*)d_in[0];
    const float* o1 = (const float*)d_in[1];
    const float* o2 = (const float*)d_in[2];
    float* out = (float*)d_out;

    build_tables<<<dim3(4, 8), 128>>>(o1, o2);
    build_matrix<<<dim3(NBIG, 4), 128>>>();
    combine<<<dim3(64, 2), 128>>>();
    fragpack<<<72, 256>>>();

    cudaFuncSetAttribute(frft_pool_main,
                         cudaFuncAttributeMaxDynamicSharedMemorySize, SMEM_BYTES);
    frft_pool_main<<<NIMG, 256, SMEM_BYTES>>>(x, out);
}

// round 17
// speedup vs baseline: 1.3067x; 1.0061x over previous
#include <cuda_runtime.h>
#include <cuda_bf16.h>
#include <math.h>
#include <cstdint>

// =====================================================================
// FrFTPool via mma.sync (sm_80 HMMA path), 5 launches (wide prep):
//  1) build_tables  2) build_matrix  3) combine  4) fragpack
//  5) frft_pool_main (512 thr: 16 warps, each m-tile x half n-tiles)
// bf16 hi/lo split folded into K (3 segments): rel err ~5e-6.
// =====================================================================

#define NBIG 128
#define NIMG 256
#define P16 136            // smem row pitch in bf16 units

__device__ __forceinline__ unsigned short bfh(float v) {
    return __bfloat16_as_ushort(__float2bfloat16_rn(v));
}
__device__ __forceinline__ float bff(unsigned short u) {
    return __bfloat162float(__ushort_as_bfloat16(u));
}
__device__ __forceinline__ void ldm_x4(uint32_t& r0, uint32_t& r1,
                                       uint32_t& r2, uint32_t& r3, uint32_t sa) {
    asm volatile("ldmatrix.sync.aligned.m8n8.x4.shared.b16 {%0,%1,%2,%3}, [%4];"
                 : "=r"(r0), "=r"(r1), "=r"(r2), "=r"(r3) : "r"(sa));
}
__device__ __forceinline__ void mma16816(float* c, uint4 a, uint32_t b0, uint32_t b1) {
    asm volatile("mma.sync.aligned.m16n8k16.row.col.f32.bf16.bf16.f32 "
                 "{%0,%1,%2,%3}, {%4,%5,%6,%7}, {%8,%9}, {%0,%1,%2,%3};"
                 : "+f"(c[0]), "+f"(c[1]), "+f"(c[2]), "+f"(c[3])
                 : "r"(a.x), "r"(a.y), "r"(a.z), "r"(a.w), "r"(b0), "r"(b1));
}

// ---------------- device scratch --------------------------------------
__device__ __align__(16) float2 d_M1[NBIG * NBIG];
__device__ __align__(16) float2 d_M2[NBIG * NBIG];
__device__ __align__(16) float2 d_M3[64 * 64];
__device__ __align__(16) float2 d_M4[64 * 64];
__device__ __align__(16) float2 d_Ac[64 * 128];       // A = M4·M2[32:96]
__device__ __align__(16) float2 d_Bc[64 * 128];       // B = M3·M1[32:96]
__device__ __align__(16) uint4  d_AF1[192 * 32];      // GEMM1 A-frags
__device__ __align__(16) uint4  d_AF2[384 * 32];      // GEMM2 A-frags

__device__ __align__(16) float2 d_Ktab[4][4 * NBIG];
__device__ __align__(16) float2 d_Ctab[4][2 * NBIG];
__device__ float2 d_pref[4];
__device__ int    d_flip[4];

// ---------------- 1) chirp tables (DP sincos, sliced over 32 blocks) --
__global__ void build_tables(const float* __restrict__ order1,
                             const float* __restrict__ order2) {
    int m = blockIdx.x;
    int s = blockIdx.y;
    int N = (m < 2) ? NBIG : 64;
    float ap = ((m == 0) || (m == 2)) ? order1[0] : order2[0];
    if (m >= 2) ap = -ap;

    double a = fmod((double)ap, 4.0);
    if (a < 0.0) a += 4.0;
    int flip = 0;
    if (a > 2.0) { flip = 1; a -= 2.0; }

    double alpha = a * M_PI * 0.5;
    double tana2 = tan(alpha * 0.5);
    double sina  = sin(alpha);
    double c     = M_PI / (4.0 * (double)N * sina);
    double kch   = (M_PI / (double)N) * tana2 * 0.25;

    int t = threadIdx.x;
    int i = s * 128 + t;
    if (i < 4 * N - 3) {
        double mm = (double)(i - (2 * N - 2));
        double sn, co; sincos(c * mm * mm, &sn, &co);
        d_Ktab[m][i] = make_float2((float)co, (float)sn);
    }
    if (t < 32) {
        int p = s * 32 + t;
        if (p < 2 * N - 1) {
            double n = (double)(p - (N - 1));
            double sn, co; sincos(-kch * n * n, &sn, &co);
            d_Ctab[m][p] = make_float2((float)co, (float)sn);
        }
    }
    if (s == 0 && t == 0) {
        double ph = -(1.0 - a) * M_PI * 0.25;
        double sn, co; sincos(ph, &sn, &co);
        double sc = sqrt(c / M_PI);
        d_pref[m] = make_float2((float)(co * sc), (float)(sn * sc));
        d_flip[m] = flip;
    }
}

// ---------------- 2) FrFT matrices from tables (fp32 only) ------------
__global__ void build_matrix() {
    int m = blockIdx.y;
    int N = (m < 2) ? NBIG : 64;
    int j = blockIdx.x;
    if (j >= N) return;

    __shared__ float2 Ks[4 * NBIG];
    __shared__ float2 Cs[2 * NBIG];
    __shared__ float  W[NBIG];
    __shared__ float2 KC[NBIG];

    int tid = threadIdx.x;
    for (int i = tid; i < 4 * N - 3; i += 128) Ks[i] = d_Ktab[m][i];
    for (int p = tid; p < 2 * N - 1; p += 128) Cs[p] = d_Ctab[m][p];
    if (tid < N)
        W[tid] = ((tid & 1) ? -2.0f : 2.0f) / ((float)M_PI * (float)(2 * tid + 1));
    __syncthreads();

    int off = 2 * N - 2;
    if (tid < N - 1) {
        float2 K = Ks[2 * j - 2 * tid - 1 + off];
        float2 C = Cs[2 * tid + 1];
        KC[tid] = make_float2(K.x * C.x - K.y * C.y, K.x * C.y + K.y * C.x);
    }
    __syncthreads();

    int k = tid;
    if (k >= N) return;
    int flip = d_flip[m];
    int kk = flip ? (N - 1 - k) : k;

    float2 Ke = Ks[2 * (j - kk) + off];
    float2 Ce = Cs[2 * kk];
    float sr = Ke.x * Ce.x - Ke.y * Ce.y;
    float si = Ke.x * Ce.y + Ke.y * Ce.x;

    #pragma unroll 4
    for (int t = 0; t < N - 1; t++) {
        int u = t - kk;
        int idx = u ^ (u >> 31);
        float sv = W[idx];
        float2 kc = KC[t];
        sr = fmaf(kc.x, sv, sr);
        si = fmaf(kc.y, sv, si);
    }

    float2 pr = d_pref[m];
    float2 Cj = Cs[2 * j];
    float pcr = pr.x * Cj.x - pr.y * Cj.y;
    float pci = pr.x * Cj.y + pr.y * Cj.x;
    float2 outv;
    outv.x = pcr * sr - pci * si;
    outv.y = pcr * si + pci * sr;

    float2* M = (m == 0) ? d_M1 : (m == 1) ? d_M2 : (m == 2) ? d_M3 : d_M4;
    M[j * N + k] = outv;
}

// ---------------- 3) combine: A = M4·M2[32:96], B = M3·M1[32:96] ------
__global__ void combine() {
    int i = blockIdx.x;          // 0..63
    int h = threadIdx.x;         // 0..127
    const float2* L = blockIdx.y ? d_M3 : d_M4;   // 64x64
    const float2* R = blockIdx.y ? d_M1 : d_M2;   // 128x128
    float ar = 0.f, ai = 0.f;
    #pragma unroll 4
    for (int p = 0; p < 64; p++) {
        float2 l2 = L[i * 64 + p];
        float2 r2 = R[(32 + p) * NBIG + h];
        ar += l2.x * r2.x - l2.y * r2.y;
        ai += l2.x * r2.y + l2.y * r2.x;
    }
    float2* T = blockIdx.y ? d_Bc : d_Ac;
    T[i * 128 + h] = make_float2(ar, ai);
}

// ---------------- 4) fragpack: constant operands -> A-frag layout ------
__device__ __forceinline__ uint32_t packB1(int n, int kk, int seg) {
    uint32_t r = 0;
    #pragma unroll
    for (int e = 0; e < 2; e++) {
        float2 b = d_Bc[(n & 63) * 128 + kk + e];
        float v = (n < 64) ? b.x : b.y;
        unsigned short hh = bfh(v);
        unsigned short u = (seg == 2) ? bfh(v - bff(hh)) : hh;
        r |= ((uint32_t)u) << (16 * e);
    }
    return r;
}
__device__ __forceinline__ uint32_t packA2(int rr, int c, int seg) {
    uint32_t r = 0;
    #pragma unroll
    for (int e = 0; e < 2; e++) {
        int cc = c + e;
        int ri = cc >> 7, p = cc & 127;
        float2 a = d_Ac[(rr & 63) * 128 + p];
        float v = (rr < 64) ? (ri ? -a.y : a.x) : (ri ? a.x : a.y);
        unsigned short hh = bfh(v);
        unsigned short u = (seg == 1) ? bfh(v - bff(hh)) : hh;
        r |= ((uint32_t)u) << (16 * e);
    }
    return r;
}
__global__ void fragpack() {
    int idx = blockIdx.x * 256 + threadIdx.x;     // < 18432
    int lane = idx & 31, t = idx >> 5;
    if (t < 192) {
        int mt = t / 24, kt = t % 24;
        int seg = kt >> 3, kb = (kt & 7) * 16;
        int r0 = 16 * mt + (lane >> 2);
        int c0 = kb + 2 * (lane & 3);
        uint4 o;
        o.x = packB1(r0,     c0,     seg);
        o.y = packB1(r0 + 8, c0,     seg);
        o.z = packB1(r0,     c0 + 8, seg);
        o.w = packB1(r0 + 8, c0 + 8, seg);
        d_AF1[t * 32 + lane] = o;
    } else {
        int t2 = t - 192;
        int mt = t2 / 48, kt = t2 % 48;
        int seg = kt >> 4;
        int k256 = (kt & 15) * 16;
        int r0 = 16 * mt + (lane >> 2);
        int c0 = k256 + 2 * (lane & 3);
        uint4 o;
        o.x = packA2(r0,     c0,     seg);
        o.y = packA2(r0 + 8, c0,     seg);
        o.z = packA2(r0,     c0 + 8, seg);
        o.w = packA2(r0 + 8, c0 + 8, seg);
        d_AF2[t2 * 32 + lane] = o;
    }
}

// ---------------- 5) main tensor kernel (512 threads, x4 LDSM) ---------
#define SMEM_BYTES (2 * 128 * P16 * 2)   // 69632

__global__ __launch_bounds__(512, 2)
void frft_pool_main(const float* __restrict__ x, float* __restrict__ out) {
    extern __shared__ char smem[];
    unsigned short* Xh = (unsigned short*)smem;   // plane0 [128][136]
    unsigned short* Xl = Xh + 128 * P16;          // plane1
    uint32_t sbase;
    {
        uint64_t g = (uint64_t)__cvta_generic_to_shared(smem);
        sbase = (uint32_t)g;
    }
    uint32_t plane0 = sbase;
    uint32_t plane1 = sbase + 128 * P16 * 2;

    int tid = threadIdx.x;
    int lane = tid & 31;
    int w = tid >> 5;           // warp 0..15
    int mt = w & 7;             // m-tile
    int ph = w >> 3;            // n-half (0/1)
    int img = blockIdx.x;
    int gr = lane >> 2;
    int gc = 2 * (lane & 3);
    uint32_t x4off = (uint32_t)((((lane & 7) + 8 * (lane >> 4)) * P16 +
                                 8 * ((lane >> 3) & 1)) * 2);

    // ---- A) load X, split to bf16 h/l planes (row-major [p][k]) ----
    const float4* xg4 = (const float4*)(x + (size_t)img * (NBIG * NBIG));
    #pragma unroll
    for (int it = 0; it < 8; it++) {
        int idx = tid + it * 512;
        int p = idx >> 5;
        int q4 = (idx & 31) << 2;
        float4 v = xg4[idx];
        unsigned short h0 = bfh(v.x), h1 = bfh(v.y), h2 = bfh(v.z), h3 = bfh(v.w);
        uint2 hv, lv;
        hv.x = (uint32_t)h0 | ((uint32_t)h1 << 16);
        hv.y = (uint32_t)h2 | ((uint32_t)h3 << 16);
        lv.x = (uint32_t)bfh(v.x - bff(h0)) | ((uint32_t)bfh(v.y - bff(h1)) << 16);
        lv.y = (uint32_t)bfh(v.z - bff(h2)) | ((uint32_t)bfh(v.w - bff(h3)) << 16);
        *(uint2*)&Xh[p * P16 + q4] = hv;
        *(uint2*)&Xl[p * P16 + q4] = lv;
    }
    __syncthreads();

    // ---- B) GEMM1: warp (mt, ph): n rows 16mt..16mt+15, p-tiles 8ph..8ph+7
    float c[8][4];
    #pragma unroll
    for (int nt = 0; nt < 8; nt++)
        #pragma unroll
        for (int r = 0; r < 4; r++) c[nt][r] = 0.f;

    #pragma unroll 4
    for (int kt = 0; kt < 24; kt++) {
        uint4 af = d_AF1[(mt * 24 + kt) * 32 + lane];
        uint32_t plane = ((kt >> 3) == 1) ? plane1 : plane0;  // X segs [h|l|h]
        int kb = (kt & 7) * 16;
        uint32_t ab = plane + x4off + (uint32_t)(kb * 2);
        #pragma unroll
        for (int ntl = 0; ntl < 8; ntl += 2) {
            int nt = 8 * ph + ntl;
            uint32_t b0, b1, b2, b3;
            ldm_x4(b0, b1, b2, b3, ab + (uint32_t)(nt * 8 * P16 * 2));
            mma16816(c[ntl],     af, b0, b1);
            mma16816(c[ntl + 1], af, b2, b3);
        }
    }
    __syncthreads();

    // ---- C) split-store T planes: T[n][p] bf16 h/l ----
    unsigned short* Th = Xh;
    unsigned short* Tl = Xl;
    #pragma unroll
    for (int ntl = 0; ntl < 8; ntl++) {
        int nt = 8 * ph + ntl;
        int p = nt * 8 + gc;
        int n0 = 16 * mt + gr;
        unsigned short hA0 = bfh(c[ntl][0]), hA1 = bfh(c[ntl][1]);
        unsigned short hB0 = bfh(c[ntl][2]), hB1 = bfh(c[ntl][3]);
        *(uint32_t*)&Th[n0 * P16 + p] =
            (uint32_t)hA0 | ((uint32_t)hA1 << 16);
        *(uint32_t*)&Tl[n0 * P16 + p] =
            (uint32_t)bfh(c[ntl][0] - bff(hA0)) |
            ((uint32_t)bfh(c[ntl][1] - bff(hA1)) << 16);
        *(uint32_t*)&Th[(n0 + 8) * P16 + p] =
            (uint32_t)hB0 | ((uint32_t)hB1 << 16);
        *(uint32_t*)&Tl[(n0 + 8) * P16 + p] =
            (uint32_t)bfh(c[ntl][2] - bff(hB0)) |
            ((uint32_t)bfh(c[ntl][3] - bff(hB1)) << 16);
    }
    __syncthreads();

    // ---- D) GEMM2: warp (mt, ph): r rows 16mt.., j-tiles 4ph..4ph+3 ----
    float d2[4][4];
    #pragma unroll
    for (int jt = 0; jt < 4; jt++)
        #pragma unroll
        for (int r = 0; r < 4; r++) d2[jt][r] = 0.f;

    #pragma unroll 4
    for (int kt = 0; kt < 48; kt++) {
        uint4 af = d_AF2[(mt * 48 + kt) * 32 + lane];
        int seg = kt >> 4;
        uint32_t plane = (seg == 2) ? plane1 : plane0;   // T segs [h|h|l]
        int k256 = (kt & 15) * 16;
        int ri = k256 >> 7, kp = k256 & 127;
        uint32_t ab = plane + x4off + (uint32_t)((64 * ri * P16 + kp) * 2);
        #pragma unroll
        for (int jtl = 0; jtl < 4; jtl += 2) {
            int jt = 4 * ph + jtl;
            uint32_t b0, b1, b2, b3;
            ldm_x4(b0, b1, b2, b3, ab + (uint32_t)(jt * 8 * P16 * 2));
            mma16816(d2[jtl],     af, b0, b1);
            mma16816(d2[jtl + 1], af, b2, b3);
        }
    }
    __syncthreads();

    // ---- E) D2 -> smem f32 [128][68] ----
    float* D2s = (float*)smem;
    #pragma unroll
    for (int jtl = 0; jtl < 4; jtl++) {
        int jt = 4 * ph + jtl;
        int j = jt * 8 + gc;
        int r0 = 16 * mt + gr;
        *(float2*)&D2s[r0 * 68 + j]       = make_float2(d2[jtl][0], d2[jtl][1]);
        *(float2*)&D2s[(r0 + 8) * 68 + j] = make_float2(d2[jtl][2], d2[jtl][3]);
    }
    __syncthreads();

    // ---- F) magnitudes ----
    float* og = out + (size_t)img * 4096;
    #pragma unroll
    for (int it = 0; it < 2; it++) {
        int idx = tid + it * 512;
        int i = idx >> 4;
        int jq = (idx & 15) << 2;
        float4 vr = *(float4*)&D2s[i * 68 + jq];
        float4 vi = *(float4*)&D2s[(i + 64) * 68 + jq];
        float4 o;
        o.x = sqrtf(vr.x * vr.x + vi.x * vi.x);
        o.y = sqrtf(vr.y * vr.y + vi.y * vi.y);
        o.z = sqrtf(vr.z * vr.z + vi.z * vi.z);
        o.w = sqrtf(vr.w * vr.w + vi.w * vi.w);
        *(float4*)&og[i * 64 + jq] = o;
    }
}

// ---------------------------------------------------------------------
extern "C" void kernel_launch(void* const* d_in, const int* in_sizes, int n_in,
                              void* d_out, int out_size) {
    const float* x  = (const float*)d_in[0];
    const float* o1 = (const float*)d_in[1];
    const float* o2 = (const float*)d_in[2];
    float* out = (float*)d_out;

    build_tables<<<dim3(4, 8), 128>>>(o1, o2);
    build_matrix<<<dim3(NBIG, 4), 128>>>();
    combine<<<dim3(64, 2), 128>>>();
    fragpack<<<72, 256>>>();

    cudaFuncSetAttribute(frft_pool_main,
                         cudaFuncAttributeMaxDynamicSharedMemorySize, SMEM_BYTES);
    frft_pool_main<<<NIMG, 512, SMEM_BYTES>>>(x, out);
}